// round 2
// baseline (speedup 1.0000x reference)
#include <cuda_runtime.h>

// VectorQuantizer: z (32,256,32,32) f32 -> 32768 rows x 256; codebook 8192x256.
// Output (f32): [0,8388608) z_q_st, [8388608] loss, [8388609,+32768) indices.
//
// Round 2: distance GEMM uses packed fma.rn.f32x2 (sm_103a FFMA2) = 2 exact
// fp32 FMAs per instruction. Per-(row,code) accumulation order is identical
// to Round 1 (sequential over d), so outputs are bitwise unchanged.

#define M_ROWS   32768
#define K_CODES  8192
#define D_DIM    256
#define ZQ_ELEMS (M_ROWS * D_DIM)
#define LOSS_OFF ZQ_ELEMS
#define IDX_OFF  (ZQ_ELEMS + 1)

#define TM 64
#define TN 128
#define TK 16
#define APAD 68
#define BPAD 132
#define KSPLIT 2
#define KC (K_CODES / KSPLIT)   /* 4096 codes per CTA */

typedef unsigned long long ull;

__device__ float  g_znorm[M_ROWS];
__device__ float  g_enorm[K_CODES];
__device__ ull    g_best[M_ROWS];   // (dist_bits<<32)|index, merged via atomicMin
__device__ double g_loss_acc;

// ---------------------------------------------------------------------------
// K1: row norms + init g_best + zero loss accumulator.
// ---------------------------------------------------------------------------
__global__ void vq_norms_kernel(const float* __restrict__ z,
                                const float* __restrict__ cb) {
    int gw   = (blockIdx.x * blockDim.x + threadIdx.x) >> 5;
    int lane = threadIdx.x & 31;
    if (gw == 0 && lane == 0) g_loss_acc = 0.0;
    if (gw >= M_ROWS + K_CODES) return;

    const float* src = (gw < M_ROWS)
                     ? (z  + (size_t)gw * D_DIM)
                     : (cb + (size_t)(gw - M_ROWS) * D_DIM);
    float s = 0.f;
#pragma unroll
    for (int i = 0; i < D_DIM / 32; ++i) {
        float v = src[lane + i * 32];
        s = __fmaf_rn(v, v, s);
    }
#pragma unroll
    for (int off = 16; off > 0; off >>= 1)
        s = __fadd_rn(s, __shfl_xor_sync(0xffffffffu, s, off));
    if (lane == 0) {
        if (gw < M_ROWS) { g_znorm[gw] = s; g_best[gw] = ~0ull; }
        else             g_enorm[gw - M_ROWS] = s;
    }
}

// ---------------------------------------------------------------------------
// K2: tiled GEMM (z @ cb^T) with FFMA2, fused running argmin.
// CTA: TM=64 rows x half the codebook (blockIdx.y). 16x16 threads, each
// computing a 4-row x 8-code micro-tile as 4x4 packed f32x2 accumulators.
// Per-(row,code) dot accumulation order identical to the scalar version.
// ---------------------------------------------------------------------------
__global__ __launch_bounds__(256, 3) void vq_argmin_kernel(
        const float* __restrict__ z, const float* __restrict__ cb) {
    __shared__ float As[TK][APAD];
    __shared__ float Bs[TK][BPAD];

    const int t  = threadIdx.x;
    const int tx = t & 15, ty = t >> 4;
    const int rowBase = blockIdx.x * TM;
    const int kcBase  = blockIdx.y * KC;

    float zn[4], bestV[4];
    int   bestI[4];
#pragma unroll
    for (int i = 0; i < 4; ++i) {
        zn[i]    = g_znorm[rowBase + ty * 4 + i];
        bestV[i] = 3.4028235e38f;
        bestI[i] = 0;
    }

    for (int ct = 0; ct < KC / TN; ++ct) {
        ull acc[4][4];
#pragma unroll
        for (int i = 0; i < 4; ++i)
#pragma unroll
            for (int jp = 0; jp < 4; ++jp) acc[i][jp] = 0ull;

        // prefetch chunk 0 into registers
        float pa[4], pb[8];
#pragma unroll
        for (int j = 0; j < 4; ++j) {
            int i = t + j * 256, r = i >> 4, d = i & 15;
            pa[j] = z[(size_t)(rowBase + r) * D_DIM + d];
        }
#pragma unroll
        for (int j = 0; j < 8; ++j) {
            int i = t + j * 256, r = i >> 4, d = i & 15;
            pb[j] = cb[(size_t)(kcBase + ct * TN + r) * D_DIM + d];
        }

        for (int db = 0; db < D_DIM / TK; ++db) {
            __syncthreads();   // previous chunk's compute done
#pragma unroll
            for (int j = 0; j < 4; ++j) {
                int i = t + j * 256;
                As[i & 15][i >> 4] = pa[j];
            }
#pragma unroll
            for (int j = 0; j < 8; ++j) {
                int i = t + j * 256;
                Bs[i & 15][i >> 4] = pb[j];
            }
            __syncthreads();

            if (db + 1 < D_DIM / TK) {   // prefetch next chunk (overlaps compute)
                int dof = (db + 1) * TK;
#pragma unroll
                for (int j = 0; j < 4; ++j) {
                    int i = t + j * 256, r = i >> 4, d = i & 15;
                    pa[j] = z[(size_t)(rowBase + r) * D_DIM + dof + d];
                }
#pragma unroll
                for (int j = 0; j < 8; ++j) {
                    int i = t + j * 256, r = i >> 4, d = i & 15;
                    pb[j] = cb[(size_t)(kcBase + ct * TN + r) * D_DIM + dof + d];
                }
            }

#pragma unroll
            for (int d = 0; d < TK; ++d) {
                float4 a4 = *reinterpret_cast<const float4*>(&As[d][ty * 4]);
                const ulonglong2* bpp =
                    reinterpret_cast<const ulonglong2*>(&Bs[d][tx * 8]);
                ulonglong2 b01 = bpp[0], b23 = bpp[1];
                ull bq[4] = {b01.x, b01.y, b23.x, b23.y};
                float av[4] = {a4.x, a4.y, a4.z, a4.w};
                ull aq[4];
#pragma unroll
                for (int i = 0; i < 4; ++i)
                    asm("mov.b64 %0, {%1, %1};" : "=l"(aq[i]) : "f"(av[i]));
#pragma unroll
                for (int i = 0; i < 4; ++i)
#pragma unroll
                    for (int jp = 0; jp < 4; ++jp)
                        asm("fma.rn.f32x2 %0, %1, %2, %3;"
                            : "=l"(acc[i][jp])
                            : "l"(aq[i]), "l"(bq[jp]), "l"(acc[i][jp]));
            }
        }

        // epilogue: d = (zn + en) - 2*dot (reference association), running min.
#pragma unroll
        for (int jp = 0; jp < 4; ++jp) {
            int   c   = kcBase + ct * TN + tx * 8 + jp * 2;
            float en0 = g_enorm[c];
            float en1 = g_enorm[c + 1];
#pragma unroll
            for (int i = 0; i < 4; ++i) {
                float dlo, dhi;
                asm("mov.b64 {%0, %1}, %2;" : "=f"(dlo), "=f"(dhi)
                                            : "l"(acc[i][jp]));
                float dv0 = __fmaf_rn(-2.f, dlo, __fadd_rn(zn[i], en0));
                float dv1 = __fmaf_rn(-2.f, dhi, __fadd_rn(zn[i], en1));
                if (dv0 < bestV[i]) { bestV[i] = dv0; bestI[i] = c; }
                if (dv1 < bestV[i]) { bestV[i] = dv1; bestI[i] = c + 1; }
            }
        }
    }

    // reduce across the 16 code-lanes per row group (tie-break lower index)
#pragma unroll
    for (int off = 8; off > 0; off >>= 1) {
#pragma unroll
        for (int i = 0; i < 4; ++i) {
            float ov = __shfl_down_sync(0xffffffffu, bestV[i], off, 16);
            int   oi = __shfl_down_sync(0xffffffffu, bestI[i], off, 16);
            if (ov < bestV[i] || (ov == bestV[i] && oi < bestI[i])) {
                bestV[i] = ov; bestI[i] = oi;
            }
        }
    }
    if (tx == 0) {
#pragma unroll
        for (int i = 0; i < 4; ++i) {
            // distances are ~||z||^2 > 0, so float-bit order == numeric order;
            // low 32 bits = index -> atomicMin ties break to the lower index.
            ull key = ((ull)__float_as_uint(bestV[i]) << 32) | (unsigned)bestI[i];
            atomicMin(&g_best[rowBase + ty * 4 + i], key);
        }
    }
}

// ---------------------------------------------------------------------------
// K3: gather z_q, straight-through output, loss accumulation, index output.
// ---------------------------------------------------------------------------
__global__ void vq_gather_kernel(const float* __restrict__ z,
                                 const float* __restrict__ cb,
                                 float* __restrict__ out, int out_size) {
    int row = blockIdx.x;
    int t   = threadIdx.x;
    int idx = (int)(unsigned)(g_best[row] & 0xffffffffull);

    float zq   = cb[(size_t)idx * D_DIM + t];
    float zv   = z [(size_t)row * D_DIM + t];
    float diff = __fadd_rn(zq, -zv);                     // fl(z_q - z)
    out[(size_t)row * D_DIM + t] = __fadd_rn(zv, diff);  // fl(z + fl(z_q - z))

    float sq = __fmul_rn(diff, diff);
#pragma unroll
    for (int off = 16; off > 0; off >>= 1)
        sq += __shfl_xor_sync(0xffffffffu, sq, off);

    __shared__ float warpS[8];
    if ((t & 31) == 0) warpS[t >> 5] = sq;
    __syncthreads();
    if (t == 0) {
        float s = 0.f;
#pragma unroll
        for (int w = 0; w < 8; ++w) s += warpS[w];
        atomicAdd(&g_loss_acc, (double)s);
        if (IDX_OFF + row < out_size) out[IDX_OFF + row] = (float)idx;
    }
}

// ---------------------------------------------------------------------------
// K4: loss = 1.25 * mean((z_q - z)^2)
// ---------------------------------------------------------------------------
__global__ void vq_finalize_kernel(float* __restrict__ out, int out_size) {
    if (LOSS_OFF < out_size)
        out[LOSS_OFF] = (float)(1.25 * g_loss_acc / (double)ZQ_ELEMS);
}

// ---------------------------------------------------------------------------
extern "C" void kernel_launch(void* const* d_in, const int* in_sizes, int n_in,
                              void* d_out, int out_size) {
    const float* z  = (const float*)d_in[0];
    const float* cb = (const float*)d_in[1];
    if (n_in >= 2 && in_sizes[0] == K_CODES * D_DIM && in_sizes[1] == ZQ_ELEMS) {
        const float* tmp = z; z = cb; cb = tmp;
    }
    float* out = (float*)d_out;

    int nwarps = M_ROWS + K_CODES;
    vq_norms_kernel<<<(nwarps * 32 + 255) / 256, 256>>>(z, cb);

    dim3 grid(M_ROWS / TM, KSPLIT);
    vq_argmin_kernel<<<grid, 256>>>(z, cb);

    vq_gather_kernel<<<M_ROWS, 256>>>(z, cb, out, out_size);
    vq_finalize_kernel<<<1, 1>>>(out, out_size);
}

// round 4
// speedup vs baseline: 3.8906x; 3.8906x over previous
#include <cuda_runtime.h>
#include <cuda_bf16.h>
#include <cstdint>

// VectorQuantizer on GB300: bf16 HMMA (mma.sync) screening GEMM + exact fp32
// rescore.  z (32768 x 256) f32, codebook (8192 x 256) f32.
// Output f32: [0,8388608) z_q_st, [8388608] loss, [8388609,+32768) indices.

#define M_ROWS   32768
#define K_CODES  8192
#define D_DIM    256
#define ZQ_ELEMS (M_ROWS * D_DIM)
#define CB_ELEMS (K_CODES * D_DIM)
#define LOSS_OFF ZQ_ELEMS
#define IDX_OFF  (ZQ_ELEMS + 1)

#define GTM 128          /* rows per CTA tile  */
#define GTN 128          /* codes per CTA tile */
#define KCH 64           /* k elements per pipeline chunk */
#define CAP 512          /* candidate slots per row */
#define MARGIN 2.5e-4f   /* ~25 sigma of bf16 screen error */

typedef unsigned long long ull;
typedef unsigned int       uint;

__device__ __nv_bfloat16 g_zbf[ZQ_ELEMS];
__device__ __nv_bfloat16 g_cbbf[CB_ELEMS];
__device__ float  g_znorm[M_ROWS];
__device__ float  g_enorm[K_CODES];
__device__ int    g_cnt[M_ROWS];
__device__ uint   g_rowmin[M_ROWS];          // order-key encoded float min
__device__ ull    g_cand[(size_t)M_ROWS * CAP];
__device__ int    g_idx[M_ROWS];
__device__ double g_loss_acc;

// ------------------------------ helpers ------------------------------------
__device__ __forceinline__ uint smem_u32(const void* p) {
    uint a;
    asm("{ .reg .u64 t; cvta.to.shared.u64 t, %1; cvt.u32.u64 %0, t; }"
        : "=r"(a) : "l"(p));
    return a;
}
#define SWZ(o) ((o) ^ (((o) >> 3) & 0x70u))   /* SW128 for 128B rows */

#define CP_ASYNC16(dst, src) \
    asm volatile("cp.async.cg.shared.global [%0], [%1], 16;" \
                 :: "r"(dst), "l"(src) : "memory")
#define CP_COMMIT() asm volatile("cp.async.commit_group;" ::: "memory")
#define CP_WAIT(n)  asm volatile("cp.async.wait_group %0;" :: "n"(n) : "memory")

#define LDSM_X4(r0, r1, r2, r3, a) \
    asm volatile("ldmatrix.sync.aligned.m8n8.x4.shared.b16 {%0,%1,%2,%3}, [%4];" \
                 : "=r"(r0), "=r"(r1), "=r"(r2), "=r"(r3) : "r"(a))

#define MMA_BF16(c, a, b) \
    asm volatile("mma.sync.aligned.m16n8k16.row.col.f32.bf16.bf16.f32 " \
                 "{%0,%1,%2,%3},{%4,%5,%6,%7},{%8,%9},{%0,%1,%2,%3};" \
                 : "+f"((c)[0]), "+f"((c)[1]), "+f"((c)[2]), "+f"((c)[3]) \
                 : "r"((a)[0]), "r"((a)[1]), "r"((a)[2]), "r"((a)[3]), \
                   "r"((b)[0]), "r"((b)[1]))

// monotonic order key for float (handles sign)
__device__ __forceinline__ uint fkey(float f) {
    uint u = __float_as_uint(f);
    return (u & 0x80000000u) ? ~u : (u | 0x80000000u);
}
__device__ __forceinline__ float keyf(uint k) {
    uint u = (k & 0x80000000u) ? (k & 0x7fffffffu) : ~k;
    return __uint_as_float(u);
}

// ---------------------------------------------------------------------------
// K0: convert z and codebook to bf16 (4 elems / thread).
// ---------------------------------------------------------------------------
__global__ void vq_convert_kernel(const float* __restrict__ z,
                                  const float* __restrict__ cb) {
    int i = blockIdx.x * blockDim.x + threadIdx.x;
    const int nz4 = ZQ_ELEMS / 4, nc4 = CB_ELEMS / 4;
    if (i < nz4) {
        float4 v = reinterpret_cast<const float4*>(z)[i];
        __nv_bfloat162 h0 = __floats2bfloat162_rn(v.x, v.y);
        __nv_bfloat162 h1 = __floats2bfloat162_rn(v.z, v.w);
        reinterpret_cast<uint2*>(g_zbf)[i] = make_uint2(*(uint*)&h0, *(uint*)&h1);
    } else if (i < nz4 + nc4) {
        int j = i - nz4;
        float4 v = reinterpret_cast<const float4*>(cb)[j];
        __nv_bfloat162 h0 = __floats2bfloat162_rn(v.x, v.y);
        __nv_bfloat162 h1 = __floats2bfloat162_rn(v.z, v.w);
        reinterpret_cast<uint2*>(g_cbbf)[j] = make_uint2(*(uint*)&h0, *(uint*)&h1);
    }
}

// ---------------------------------------------------------------------------
// K1: row norms (warp/row) + per-row state init + zero loss accumulator.
// ---------------------------------------------------------------------------
__global__ void vq_norms_kernel(const float* __restrict__ z,
                                const float* __restrict__ cb) {
    int gw   = (blockIdx.x * blockDim.x + threadIdx.x) >> 5;
    int lane = threadIdx.x & 31;
    if (gw == 0 && lane == 0) g_loss_acc = 0.0;
    if (gw >= M_ROWS + K_CODES) return;

    const float* src = (gw < M_ROWS) ? (z + (size_t)gw * D_DIM)
                                     : (cb + (size_t)(gw - M_ROWS) * D_DIM);
    float s = 0.f;
#pragma unroll
    for (int i = 0; i < D_DIM / 32; ++i) {
        float v = src[lane + i * 32];
        s = __fmaf_rn(v, v, s);
    }
#pragma unroll
    for (int off = 16; off > 0; off >>= 1)
        s = __fadd_rn(s, __shfl_xor_sync(0xffffffffu, s, off));
    if (lane == 0) {
        if (gw < M_ROWS) {
            g_znorm[gw]  = s;
            g_cnt[gw]    = 0;
            g_rowmin[gw] = 0xFFFFFFFFu;
        } else {
            g_enorm[gw - M_ROWS] = s;
        }
    }
}

// ---------------------------------------------------------------------------
// K2: screening GEMM via bf16 mma.sync.  CTA = 128 rows x 128 codes, K=256
// in 4 cp.async double-buffered chunks of 64.  8 warps as 2(m) x 4(n),
// warp tile 64x32 (m16n8k16 frags: 4 mi x 4 ni).
// Epilogue: d_s = enorm - 2*dot; per-tile row-min in smem; collect codes
// within MARGIN of the tile row-min.
// ---------------------------------------------------------------------------
#define ABYTES (GTM * KCH * 2)   /* 16384 */
#define BBYTES (GTN * KCH * 2)   /* 16384 */
#define SMEM_DYN (1024 + 2 * (ABYTES + BBYTES))

__device__ __forceinline__ void screen_load_chunk(uint aU, uint bU,
                                                  int rowBase, int kcBase,
                                                  int kc, int tid) {
#pragma unroll
    for (int i = 0; i < 4; ++i) {               // A: 128 rows x 8 16B-chunks
        int id = i * 256 + tid;
        int r = id >> 3, c = id & 7;
        const __nv_bfloat16* src =
            g_zbf + (size_t)(rowBase + r) * D_DIM + kc * KCH + c * 8;
        uint off = (uint)(r * 128 + c * 16);
        CP_ASYNC16(aU + SWZ(off), src);
    }
#pragma unroll
    for (int i = 0; i < 4; ++i) {               // B: 128 codes x 8 chunks
        int id = i * 256 + tid;
        int r = id >> 3, c = id & 7;
        const __nv_bfloat16* src =
            g_cbbf + (size_t)(kcBase + r) * D_DIM + kc * KCH + c * 8;
        uint off = (uint)(r * 128 + c * 16);
        CP_ASYNC16(bU + SWZ(off), src);
    }
}

__global__ __launch_bounds__(256) void vq_screen_kernel() {
    extern __shared__ __align__(16) char dynsmem[];
    __shared__ uint  s_rowmin[GTM];
    __shared__ float en_s[GTN];

    const int tid  = threadIdx.x;
    const int wid  = tid >> 5, lane = tid & 31;
    const int rowBase = blockIdx.x * GTM;
    const int kcBase  = blockIdx.y * GTN;
    const int warp_m  = (wid >> 2) * 64;
    const int warp_n  = (wid & 3) * 32;

    uint base = smem_u32(dynsmem);
    uint tile0 = (base + 1023u) & ~1023u;
    // layout: [A0][B0][A1][B1]
    uint aU[2] = { tile0,                    tile0 + ABYTES + BBYTES };
    uint bU[2] = { tile0 + ABYTES,           tile0 + 2 * ABYTES + BBYTES };

    if (tid < GTM) s_rowmin[tid] = 0xFFFFFFFFu;
    if (tid < GTN) en_s[tid] = g_enorm[kcBase + tid];

    float acc[4][4][4];
#pragma unroll
    for (int mi = 0; mi < 4; ++mi)
#pragma unroll
        for (int ni = 0; ni < 4; ++ni)
#pragma unroll
            for (int q = 0; q < 4; ++q) acc[mi][ni][q] = 0.f;

    screen_load_chunk(aU[0], bU[0], rowBase, kcBase, 0, tid);
    CP_COMMIT();

    for (int c = 0; c < D_DIM / KCH; ++c) {
        if (c + 1 < D_DIM / KCH) {
            screen_load_chunk(aU[(c + 1) & 1], bU[(c + 1) & 1],
                              rowBase, kcBase, c + 1, tid);
            CP_COMMIT();
            CP_WAIT(1);
        } else {
            CP_WAIT(0);
        }
        __syncthreads();

        uint aT = aU[c & 1], bT = bU[c & 1];
#pragma unroll
        for (int ks = 0; ks < KCH / 16; ++ks) {
            uint afr[4][4];
#pragma unroll
            for (int mi = 0; mi < 4; ++mi) {
                uint off = (uint)((warp_m + mi * 16 + (lane & 15)) * 128
                                  + ks * 32 + (lane >> 4) * 16);
                LDSM_X4(afr[mi][0], afr[mi][1], afr[mi][2], afr[mi][3],
                        aT + SWZ(off));
            }
            uint bfr[4][2];
#pragma unroll
            for (int np = 0; np < 2; ++np) {
                uint off = (uint)((warp_n + np * 16 + (lane & 7)
                                   + ((lane >> 4) & 1) * 8) * 128
                                  + ks * 32 + ((lane >> 3) & 1) * 16);
                LDSM_X4(bfr[np * 2][0], bfr[np * 2][1],
                        bfr[np * 2 + 1][0], bfr[np * 2 + 1][1],
                        bT + SWZ(off));
            }
#pragma unroll
            for (int mi = 0; mi < 4; ++mi)
#pragma unroll
                for (int ni = 0; ni < 4; ++ni)
                    MMA_BF16(acc[mi][ni], afr[mi], bfr[ni]);
        }
        __syncthreads();
    }

    // ---- epilogue pass 1: d = en - 2*dot, per-tile row minimum -------------
#pragma unroll
    for (int mi = 0; mi < 4; ++mi) {
#pragma unroll
        for (int h = 0; h < 2; ++h) {
            float m = 3.4028235e38f;
#pragma unroll
            for (int ni = 0; ni < 4; ++ni)
#pragma unroll
                for (int j = 0; j < 2; ++j) {
                    int q = h * 2 + j;
                    float en = en_s[warp_n + ni * 8 + (lane & 3) * 2 + j];
                    float d  = __fmaf_rn(-2.f, acc[mi][ni][q], en);
                    acc[mi][ni][q] = d;
                    m = fminf(m, d);
                }
            int rl = warp_m + mi * 16 + h * 8 + (lane >> 2);
            atomicMin(&s_rowmin[rl], fkey(m));
        }
    }
    __syncthreads();

    // ---- epilogue pass 2: collect candidates within MARGIN of tile min ----
#pragma unroll
    for (int mi = 0; mi < 4; ++mi) {
#pragma unroll
        for (int h = 0; h < 2; ++h) {
            int   rl  = warp_m + mi * 16 + h * 8 + (lane >> 2);
            int   row = rowBase + rl;
            float thr = keyf(s_rowmin[rl]) + MARGIN;
#pragma unroll
            for (int ni = 0; ni < 4; ++ni)
#pragma unroll
                for (int j = 0; j < 2; ++j) {
                    float d = acc[mi][ni][h * 2 + j];
                    if (d < thr) {
                        int code = kcBase + warp_n + ni * 8 + (lane & 3) * 2 + j;
                        int pos = atomicAdd(&g_cnt[row], 1);
                        if (pos < CAP)
                            g_cand[(size_t)row * CAP + pos] =
                                ((ull)__float_as_uint(d) << 32) | (uint)code;
                    }
                }
        }
    }
    if (tid < GTM)
        atomicMin(&g_rowmin[rowBase + tid], s_rowmin[tid]);
}

// ---------------------------------------------------------------------------
// K3: exact rescore.  One warp per row.
// ---------------------------------------------------------------------------
__global__ void vq_rescore_kernel(const float* __restrict__ z,
                                  const float* __restrict__ cb) {
    int gw   = (blockIdx.x * blockDim.x + threadIdx.x) >> 5;
    int lane = threadIdx.x & 31;
    if (gw >= M_ROWS) return;
    int row = gw;

    float zn     = g_znorm[row];
    float thresh = keyf(g_rowmin[row]) + MARGIN;
    int   cnt    = g_cnt[row];

    const float* zr = z + (size_t)row * D_DIM;
    float bestv = 3.4028235e38f;
    int   besti = K_CODES;

    if (cnt <= CAP) {
        for (int b = 0; b < cnt; b += 32) {
            int  i = b + lane;
            int  c = 0;
            bool q = false;
            if (i < cnt) {
                ull e = g_cand[(size_t)row * CAP + i];
                q = __uint_as_float((uint)(e >> 32)) < thresh;
                c = (int)(uint)(e & 0xffffffffull);
            }
            uint bal = __ballot_sync(0xffffffffu, q);
            while (bal) {
                int src = __ffs(bal) - 1; bal &= bal - 1;
                int cc  = __shfl_sync(0xffffffffu, c, src);
                const float* er = cb + (size_t)cc * D_DIM;
                float p = 0.f;
#pragma unroll
                for (int k = 0; k < 8; ++k)
                    p = __fmaf_rn(zr[lane + 32 * k], er[lane + 32 * k], p);
#pragma unroll
                for (int off = 16; off > 0; off >>= 1)
                    p = __fadd_rn(p, __shfl_xor_sync(0xffffffffu, p, off));
                float dv = __fmaf_rn(-2.f, p, __fadd_rn(zn, g_enorm[cc]));
                if (dv < bestv || (dv == bestv && cc < besti)) {
                    bestv = dv; besti = cc;
                }
            }
        }
    } else {
        // overflow fallback (expected never): exact scan of all codes
        for (int cc = 0; cc < K_CODES; ++cc) {
            const float* er = cb + (size_t)cc * D_DIM;
            float p = 0.f;
#pragma unroll
            for (int k = 0; k < 8; ++k)
                p = __fmaf_rn(zr[lane + 32 * k], er[lane + 32 * k], p);
#pragma unroll
            for (int off = 16; off > 0; off >>= 1)
                p = __fadd_rn(p, __shfl_xor_sync(0xffffffffu, p, off));
            float dv = __fmaf_rn(-2.f, p, __fadd_rn(zn, g_enorm[cc]));
            if (dv < bestv) { bestv = dv; besti = cc; }
        }
    }
    if (lane == 0) g_idx[row] = besti;
}

// ---------------------------------------------------------------------------
// K4: gather z_q, straight-through output, loss accumulation, index output.
// ---------------------------------------------------------------------------
__global__ void vq_gather_kernel(const float* __restrict__ z,
                                 const float* __restrict__ cb,
                                 float* __restrict__ out, int out_size) {
    int row = blockIdx.x;
    int t   = threadIdx.x;
    int idx = g_idx[row];

    float zq   = cb[(size_t)idx * D_DIM + t];
    float zv   = z [(size_t)row * D_DIM + t];
    float diff = __fadd_rn(zq, -zv);
    out[(size_t)row * D_DIM + t] = __fadd_rn(zv, diff);

    float sq = __fmul_rn(diff, diff);
#pragma unroll
    for (int off = 16; off > 0; off >>= 1)
        sq += __shfl_xor_sync(0xffffffffu, sq, off);

    __shared__ float warpS[8];
    if ((t & 31) == 0) warpS[t >> 5] = sq;
    __syncthreads();
    if (t == 0) {
        float s = 0.f;
#pragma unroll
        for (int w = 0; w < 8; ++w) s += warpS[w];
        atomicAdd(&g_loss_acc, (double)s);
        if (IDX_OFF + row < out_size) out[IDX_OFF + row] = (float)idx;
    }
}

__global__ void vq_finalize_kernel(float* __restrict__ out, int out_size) {
    if (LOSS_OFF < out_size)
        out[LOSS_OFF] = (float)(1.25 * g_loss_acc / (double)ZQ_ELEMS);
}

// ---------------------------------------------------------------------------
extern "C" void kernel_launch(void* const* d_in, const int* in_sizes, int n_in,
                              void* d_out, int out_size) {
    const float* z  = (const float*)d_in[0];
    const float* cb = (const float*)d_in[1];
    if (n_in >= 2 && in_sizes[0] == CB_ELEMS && in_sizes[1] == ZQ_ELEMS) {
        const float* tmp = z; z = cb; cb = tmp;
    }
    float* out = (float*)d_out;

    static bool attr_set = false;   // idempotent host-side attribute set
    if (!attr_set) {
        cudaFuncSetAttribute(vq_screen_kernel,
                             cudaFuncAttributeMaxDynamicSharedMemorySize,
                             SMEM_DYN);
        attr_set = true;
    }

    int n4 = (ZQ_ELEMS + CB_ELEMS) / 4;
    vq_convert_kernel<<<(n4 + 255) / 256, 256>>>(z, cb);

    int nwarps = M_ROWS + K_CODES;
    vq_norms_kernel<<<(nwarps * 32 + 255) / 256, 256>>>(z, cb);

    dim3 sgrid(M_ROWS / GTM, K_CODES / GTN);
    vq_screen_kernel<<<sgrid, 256, SMEM_DYN>>>();

    vq_rescore_kernel<<<(M_ROWS * 32 + 255) / 256, 256>>>(z, cb);

    vq_gather_kernel<<<M_ROWS, 256>>>(z, cb, out, out_size);
    vq_finalize_kernel<<<1, 1>>>(out, out_size);
}

// round 5
// speedup vs baseline: 5.6598x; 1.4548x over previous
#include <cuda_runtime.h>
#include <cuda_bf16.h>
#include <cstdint>

// VectorQuantizer on GB300: bf16 HMMA (mma.sync) screening GEMM + exact fp32
// rescore.  z (32768 x 256) f32, codebook (8192 x 256) f32.
// Output f32: [0,8388608) z_q_st, [8388608] loss, [8388609,+32768) indices.
// R5: 3-stage cp.async pipeline, one barrier per chunk, 2 CTAs/SM.

#define M_ROWS   32768
#define K_CODES  8192
#define D_DIM    256
#define ZQ_ELEMS (M_ROWS * D_DIM)
#define CB_ELEMS (K_CODES * D_DIM)
#define LOSS_OFF ZQ_ELEMS
#define IDX_OFF  (ZQ_ELEMS + 1)

#define GTM 128          /* rows per CTA tile  */
#define GTN 128          /* codes per CTA tile */
#define KCH 64           /* k elements per pipeline chunk */
#define NCHUNK (D_DIM / KCH)   /* 4 */
#define CAP 512          /* candidate slots per row */
#define MARGIN 2.5e-4f   /* ~25 sigma of bf16 screen error */

typedef unsigned long long ull;
typedef unsigned int       uint;

__device__ __nv_bfloat16 g_zbf[ZQ_ELEMS];
__device__ __nv_bfloat16 g_cbbf[CB_ELEMS];
__device__ float  g_znorm[M_ROWS];
__device__ float  g_enorm[K_CODES];
__device__ int    g_cnt[M_ROWS];
__device__ uint   g_rowmin[M_ROWS];          // order-key encoded float min
__device__ ull    g_cand[(size_t)M_ROWS * CAP];
__device__ int    g_idx[M_ROWS];
__device__ double g_loss_acc;

// ------------------------------ helpers ------------------------------------
__device__ __forceinline__ uint smem_u32(const void* p) {
    uint a;
    asm("{ .reg .u64 t; cvta.to.shared.u64 t, %1; cvt.u32.u64 %0, t; }"
        : "=r"(a) : "l"(p));
    return a;
}
#define SWZ(o) ((o) ^ (((o) >> 3) & 0x70u))   /* SW128 for 128B rows */

#define CP_ASYNC16(dst, src) \
    asm volatile("cp.async.cg.shared.global [%0], [%1], 16;" \
                 :: "r"(dst), "l"(src) : "memory")
#define CP_COMMIT() asm volatile("cp.async.commit_group;" ::: "memory")
#define CP_WAIT(n)  asm volatile("cp.async.wait_group %0;" :: "n"(n) : "memory")

#define LDSM_X4(r0, r1, r2, r3, a) \
    asm volatile("ldmatrix.sync.aligned.m8n8.x4.shared.b16 {%0,%1,%2,%3}, [%4];" \
                 : "=r"(r0), "=r"(r1), "=r"(r2), "=r"(r3) : "r"(a))

#define MMA_BF16(c, a, b) \
    asm volatile("mma.sync.aligned.m16n8k16.row.col.f32.bf16.bf16.f32 " \
                 "{%0,%1,%2,%3},{%4,%5,%6,%7},{%8,%9},{%0,%1,%2,%3};" \
                 : "+f"((c)[0]), "+f"((c)[1]), "+f"((c)[2]), "+f"((c)[3]) \
                 : "r"((a)[0]), "r"((a)[1]), "r"((a)[2]), "r"((a)[3]), \
                   "r"((b)[0]), "r"((b)[1]))

// monotonic order key for float (handles sign)
__device__ __forceinline__ uint fkey(float f) {
    uint u = __float_as_uint(f);
    return (u & 0x80000000u) ? ~u : (u | 0x80000000u);
}
__device__ __forceinline__ float keyf(uint k) {
    uint u = (k & 0x80000000u) ? (k & 0x7fffffffu) : ~k;
    return __uint_as_float(u);
}

// ---------------------------------------------------------------------------
// K0: convert z and codebook to bf16 (4 elems / thread).
// ---------------------------------------------------------------------------
__global__ void vq_convert_kernel(const float* __restrict__ z,
                                  const float* __restrict__ cb) {
    int i = blockIdx.x * blockDim.x + threadIdx.x;
    const int nz4 = ZQ_ELEMS / 4, nc4 = CB_ELEMS / 4;
    if (i < nz4) {
        float4 v = reinterpret_cast<const float4*>(z)[i];
        __nv_bfloat162 h0 = __floats2bfloat162_rn(v.x, v.y);
        __nv_bfloat162 h1 = __floats2bfloat162_rn(v.z, v.w);
        reinterpret_cast<uint2*>(g_zbf)[i] = make_uint2(*(uint*)&h0, *(uint*)&h1);
    } else if (i < nz4 + nc4) {
        int j = i - nz4;
        float4 v = reinterpret_cast<const float4*>(cb)[j];
        __nv_bfloat162 h0 = __floats2bfloat162_rn(v.x, v.y);
        __nv_bfloat162 h1 = __floats2bfloat162_rn(v.z, v.w);
        reinterpret_cast<uint2*>(g_cbbf)[j] = make_uint2(*(uint*)&h0, *(uint*)&h1);
    }
}

// ---------------------------------------------------------------------------
// K1: row norms (warp/row) + per-row state init + zero loss accumulator.
// ---------------------------------------------------------------------------
__global__ void vq_norms_kernel(const float* __restrict__ z,
                                const float* __restrict__ cb) {
    int gw   = (blockIdx.x * blockDim.x + threadIdx.x) >> 5;
    int lane = threadIdx.x & 31;
    if (gw == 0 && lane == 0) g_loss_acc = 0.0;
    if (gw >= M_ROWS + K_CODES) return;

    const float* src = (gw < M_ROWS) ? (z + (size_t)gw * D_DIM)
                                     : (cb + (size_t)(gw - M_ROWS) * D_DIM);
    float s = 0.f;
#pragma unroll
    for (int i = 0; i < D_DIM / 32; ++i) {
        float v = src[lane + i * 32];
        s = __fmaf_rn(v, v, s);
    }
#pragma unroll
    for (int off = 16; off > 0; off >>= 1)
        s = __fadd_rn(s, __shfl_xor_sync(0xffffffffu, s, off));
    if (lane == 0) {
        if (gw < M_ROWS) {
            g_znorm[gw]  = s;
            g_cnt[gw]    = 0;
            g_rowmin[gw] = 0xFFFFFFFFu;
        } else {
            g_enorm[gw - M_ROWS] = s;
        }
    }
}

// ---------------------------------------------------------------------------
// K2: screening GEMM via bf16 mma.sync.  CTA = 128 rows x 128 codes, K=256
// in 4 chunks of 64 through a 3-stage cp.async ring (ONE barrier per chunk).
// 8 warps as 2(m) x 4(n), warp tile 64x32 (m16n8k16 frags: 4 mi x 4 ni).
// Epilogue: d_s = enorm - 2*dot; per-tile row-min in smem; collect codes
// within MARGIN of the tile row-min.
// ---------------------------------------------------------------------------
#define ABYTES (GTM * KCH * 2)   /* 16384 */
#define BBYTES (GTN * KCH * 2)   /* 16384 */
#define STG    (ABYTES + BBYTES) /* 32768 per stage */
#define NSTAGE 3
#define SMEM_DYN (1024 + NSTAGE * STG)

__device__ __forceinline__ void screen_load_chunk(uint aU, uint bU,
                                                  int rowBase, int kcBase,
                                                  int kc, int tid) {
#pragma unroll
    for (int i = 0; i < 4; ++i) {               // A: 128 rows x 8 16B-chunks
        int id = i * 256 + tid;
        int r = id >> 3, c = id & 7;
        const __nv_bfloat16* src =
            g_zbf + (size_t)(rowBase + r) * D_DIM + kc * KCH + c * 8;
        uint off = (uint)(r * 128 + c * 16);
        CP_ASYNC16(aU + SWZ(off), src);
    }
#pragma unroll
    for (int i = 0; i < 4; ++i) {               // B: 128 codes x 8 chunks
        int id = i * 256 + tid;
        int r = id >> 3, c = id & 7;
        const __nv_bfloat16* src =
            g_cbbf + (size_t)(kcBase + r) * D_DIM + kc * KCH + c * 8;
        uint off = (uint)(r * 128 + c * 16);
        CP_ASYNC16(bU + SWZ(off), src);
    }
}

__global__ __launch_bounds__(256, 2) void vq_screen_kernel() {
    extern __shared__ __align__(16) char dynsmem[];
    __shared__ uint  s_rowmin[GTM];
    __shared__ float en_s[GTN];

    const int tid  = threadIdx.x;
    const int wid  = tid >> 5, lane = tid & 31;
    const int rowBase = blockIdx.x * GTM;
    const int kcBase  = blockIdx.y * GTN;
    const int warp_m  = (wid >> 2) * 64;
    const int warp_n  = (wid & 3) * 32;

    uint base  = smem_u32(dynsmem);
    uint tile0 = (base + 1023u) & ~1023u;

    if (tid < GTM) s_rowmin[tid] = 0xFFFFFFFFu;
    if (tid < GTN) en_s[tid] = g_enorm[kcBase + tid];

    float acc[4][4][4];
#pragma unroll
    for (int mi = 0; mi < 4; ++mi)
#pragma unroll
        for (int ni = 0; ni < 4; ++ni)
#pragma unroll
            for (int q = 0; q < 4; ++q) acc[mi][ni][q] = 0.f;

    // prologue: fill 2 of the 3 stages
    screen_load_chunk(tile0,       tile0 + ABYTES,       rowBase, kcBase, 0, tid);
    CP_COMMIT();
    screen_load_chunk(tile0 + STG, tile0 + STG + ABYTES, rowBase, kcBase, 1, tid);
    CP_COMMIT();

#pragma unroll
    for (int c = 0; c < NCHUNK; ++c) {
        if (c < NCHUNK - 1) { CP_WAIT(1); } else { CP_WAIT(0); }
        __syncthreads();   // chunk c resident for all threads; and all warps
                           // finished reading stage (c+2)%3 (iter c-1 compute)

        if (c + 2 < NCHUNK) {
            uint st = tile0 + ((c + 2) % NSTAGE) * STG;
            screen_load_chunk(st, st + ABYTES, rowBase, kcBase, c + 2, tid);
            CP_COMMIT();
        }

        uint aT = tile0 + (c % NSTAGE) * STG;
        uint bT = aT + ABYTES;
#pragma unroll
        for (int ks = 0; ks < KCH / 16; ++ks) {
            uint afr[4][4];
#pragma unroll
            for (int mi = 0; mi < 4; ++mi) {
                uint off = (uint)((warp_m + mi * 16 + (lane & 15)) * 128
                                  + ks * 32 + (lane >> 4) * 16);
                LDSM_X4(afr[mi][0], afr[mi][1], afr[mi][2], afr[mi][3],
                        aT + SWZ(off));
            }
            uint bfr[4][2];
#pragma unroll
            for (int np = 0; np < 2; ++np) {
                uint off = (uint)((warp_n + np * 16 + (lane & 7)
                                   + ((lane >> 4) & 1) * 8) * 128
                                  + ks * 32 + ((lane >> 3) & 1) * 16);
                LDSM_X4(bfr[np * 2][0], bfr[np * 2][1],
                        bfr[np * 2 + 1][0], bfr[np * 2 + 1][1],
                        bT + SWZ(off));
            }
#pragma unroll
            for (int mi = 0; mi < 4; ++mi)
#pragma unroll
                for (int ni = 0; ni < 4; ++ni)
                    MMA_BF16(acc[mi][ni], afr[mi], bfr[ni]);
        }
    }
    __syncthreads();   // compute done before epilogue touches s_rowmin

    // ---- epilogue pass 1: d = en - 2*dot, per-tile row minimum -------------
#pragma unroll
    for (int mi = 0; mi < 4; ++mi) {
#pragma unroll
        for (int h = 0; h < 2; ++h) {
            float m = 3.4028235e38f;
#pragma unroll
            for (int ni = 0; ni < 4; ++ni)
#pragma unroll
                for (int j = 0; j < 2; ++j) {
                    int q = h * 2 + j;
                    float en = en_s[warp_n + ni * 8 + (lane & 3) * 2 + j];
                    float d  = __fmaf_rn(-2.f, acc[mi][ni][q], en);
                    acc[mi][ni][q] = d;
                    m = fminf(m, d);
                }
            int rl = warp_m + mi * 16 + h * 8 + (lane >> 2);
            atomicMin(&s_rowmin[rl], fkey(m));
        }
    }
    __syncthreads();

    // ---- epilogue pass 2: collect candidates within MARGIN of tile min ----
#pragma unroll
    for (int mi = 0; mi < 4; ++mi) {
#pragma unroll
        for (int h = 0; h < 2; ++h) {
            int   rl  = warp_m + mi * 16 + h * 8 + (lane >> 2);
            int   row = rowBase + rl;
            float thr = keyf(s_rowmin[rl]) + MARGIN;
#pragma unroll
            for (int ni = 0; ni < 4; ++ni)
#pragma unroll
                for (int j = 0; j < 2; ++j) {
                    float d = acc[mi][ni][h * 2 + j];
                    if (d < thr) {
                        int code = kcBase + warp_n + ni * 8 + (lane & 3) * 2 + j;
                        int pos = atomicAdd(&g_cnt[row], 1);
                        if (pos < CAP)
                            g_cand[(size_t)row * CAP + pos] =
                                ((ull)__float_as_uint(d) << 32) | (uint)code;
                    }
                }
        }
    }
    if (tid < GTM)
        atomicMin(&g_rowmin[rowBase + tid], s_rowmin[tid]);
}

// ---------------------------------------------------------------------------
// K3: exact rescore.  One warp per row.
// ---------------------------------------------------------------------------
__global__ void vq_rescore_kernel(const float* __restrict__ z,
                                  const float* __restrict__ cb) {
    int gw   = (blockIdx.x * blockDim.x + threadIdx.x) >> 5;
    int lane = threadIdx.x & 31;
    if (gw >= M_ROWS) return;
    int row = gw;

    float zn     = g_znorm[row];
    float thresh = keyf(g_rowmin[row]) + MARGIN;
    int   cnt    = g_cnt[row];

    const float* zr = z + (size_t)row * D_DIM;
    float bestv = 3.4028235e38f;
    int   besti = K_CODES;

    if (cnt <= CAP) {
        for (int b = 0; b < cnt; b += 32) {
            int  i = b + lane;
            int  c = 0;
            bool q = false;
            if (i < cnt) {
                ull e = g_cand[(size_t)row * CAP + i];
                q = __uint_as_float((uint)(e >> 32)) < thresh;
                c = (int)(uint)(e & 0xffffffffull);
            }
            uint bal = __ballot_sync(0xffffffffu, q);
            while (bal) {
                int src = __ffs(bal) - 1; bal &= bal - 1;
                int cc  = __shfl_sync(0xffffffffu, c, src);
                const float* er = cb + (size_t)cc * D_DIM;
                float p = 0.f;
#pragma unroll
                for (int k = 0; k < 8; ++k)
                    p = __fmaf_rn(zr[lane + 32 * k], er[lane + 32 * k], p);
#pragma unroll
                for (int off = 16; off > 0; off >>= 1)
                    p = __fadd_rn(p, __shfl_xor_sync(0xffffffffu, p, off));
                float dv = __fmaf_rn(-2.f, p, __fadd_rn(zn, g_enorm[cc]));
                if (dv < bestv || (dv == bestv && cc < besti)) {
                    bestv = dv; besti = cc;
                }
            }
        }
    } else {
        // overflow fallback (expected never): exact scan of all codes
        for (int cc = 0; cc < K_CODES; ++cc) {
            const float* er = cb + (size_t)cc * D_DIM;
            float p = 0.f;
#pragma unroll
            for (int k = 0; k < 8; ++k)
                p = __fmaf_rn(zr[lane + 32 * k], er[lane + 32 * k], p);
#pragma unroll
            for (int off = 16; off > 0; off >>= 1)
                p = __fadd_rn(p, __shfl_xor_sync(0xffffffffu, p, off));
            float dv = __fmaf_rn(-2.f, p, __fadd_rn(zn, g_enorm[cc]));
            if (dv < bestv) { bestv = dv; besti = cc; }
        }
    }
    if (lane == 0) g_idx[row] = besti;
}

// ---------------------------------------------------------------------------
// K4: gather z_q, straight-through output, loss accumulation, index output.
// ---------------------------------------------------------------------------
__global__ void vq_gather_kernel(const float* __restrict__ z,
                                 const float* __restrict__ cb,
                                 float* __restrict__ out, int out_size) {
    int row = blockIdx.x;
    int t   = threadIdx.x;
    int idx = g_idx[row];

    float zq   = cb[(size_t)idx * D_DIM + t];
    float zv   = z [(size_t)row * D_DIM + t];
    float diff = __fadd_rn(zq, -zv);
    out[(size_t)row * D_DIM + t] = __fadd_rn(zv, diff);

    float sq = __fmul_rn(diff, diff);
#pragma unroll
    for (int off = 16; off > 0; off >>= 1)
        sq += __shfl_xor_sync(0xffffffffu, sq, off);

    __shared__ float warpS[8];
    if ((t & 31) == 0) warpS[t >> 5] = sq;
    __syncthreads();
    if (t == 0) {
        float s = 0.f;
#pragma unroll
        for (int w = 0; w < 8; ++w) s += warpS[w];
        atomicAdd(&g_loss_acc, (double)s);
        if (IDX_OFF + row < out_size) out[IDX_OFF + row] = (float)idx;
    }
}

__global__ void vq_finalize_kernel(float* __restrict__ out, int out_size) {
    if (LOSS_OFF < out_size)
        out[LOSS_OFF] = (float)(1.25 * g_loss_acc / (double)ZQ_ELEMS);
}

// ---------------------------------------------------------------------------
extern "C" void kernel_launch(void* const* d_in, const int* in_sizes, int n_in,
                              void* d_out, int out_size) {
    const float* z  = (const float*)d_in[0];
    const float* cb = (const float*)d_in[1];
    if (n_in >= 2 && in_sizes[0] == CB_ELEMS && in_sizes[1] == ZQ_ELEMS) {
        const float* tmp = z; z = cb; cb = tmp;
    }
    float* out = (float*)d_out;

    static bool attr_set = false;   // idempotent host-side attribute set
    if (!attr_set) {
        cudaFuncSetAttribute(vq_screen_kernel,
                             cudaFuncAttributeMaxDynamicSharedMemorySize,
                             SMEM_DYN);
        attr_set = true;
    }

    int n4 = (ZQ_ELEMS + CB_ELEMS) / 4;
    vq_convert_kernel<<<(n4 + 255) / 256, 256>>>(z, cb);

    int nwarps = M_ROWS + K_CODES;
    vq_norms_kernel<<<(nwarps * 32 + 255) / 256, 256>>>(z, cb);

    dim3 sgrid(M_ROWS / GTM, K_CODES / GTN);
    vq_screen_kernel<<<sgrid, 256, SMEM_DYN>>>();

    vq_rescore_kernel<<<(M_ROWS * 32 + 255) / 256, 256>>>(z, cb);

    vq_gather_kernel<<<M_ROWS, 256>>>(z, cb, out, out_size);
    vq_finalize_kernel<<<1, 1>>>(out, out_size);
}

// round 6
// speedup vs baseline: 8.4464x; 1.4923x over previous
#include <cuda_runtime.h>
#include <cuda_bf16.h>
#include <cstdint>

// VectorQuantizer on GB300: bf16 HMMA screening GEMM + exact fp32 rescore.
// R6: A-resident screen — each CTA pins a 128-row z tile in smem and streams
// 4096 codebook rows through a 2-stage cp.async ring (1 barrier/chunk).
// Halves L2 tile traffic and cp.async issue vs R5.

#define M_ROWS   32768
#define K_CODES  8192
#define D_DIM    256
#define ZQ_ELEMS (M_ROWS * D_DIM)
#define CB_ELEMS (K_CODES * D_DIM)
#define LOSS_OFF ZQ_ELEMS
#define IDX_OFF  (ZQ_ELEMS + 1)

#define GTM 128            /* rows per CTA                  */
#define GTN 128            /* codes per subtile             */
#define NSPLIT 2           /* codebook split across CTAs    */
#define CPC (K_CODES / NSPLIT)      /* 4096 codes per CTA   */
#define NSUB (CPC / GTN)            /* 32 subtiles          */
#define KCH 64             /* dims per B chunk              */
#define NCHUNK (NSUB * (D_DIM / KCH))   /* 128 B chunks     */
#define CAP 512
#define MARGIN 2.5e-4f     /* ~25 sigma of bf16 screen error */

typedef unsigned long long ull;
typedef unsigned int       uint;

__device__ __nv_bfloat16 g_zbf[ZQ_ELEMS];
__device__ __nv_bfloat16 g_cbbf[CB_ELEMS];
__device__ float  g_znorm[M_ROWS];
__device__ float  g_enorm[K_CODES];
__device__ int    g_cnt[M_ROWS];
__device__ uint   g_rowmin[M_ROWS];
__device__ ull    g_cand[(size_t)M_ROWS * CAP];
__device__ int    g_idx[M_ROWS];
__device__ double g_loss_acc;

// ------------------------------ helpers ------------------------------------
__device__ __forceinline__ uint smem_u32(const void* p) {
    uint a;
    asm("{ .reg .u64 t; cvta.to.shared.u64 t, %1; cvt.u32.u64 %0, t; }"
        : "=r"(a) : "l"(p));
    return a;
}
#define SWZ(o) ((o) ^ (((o) >> 3) & 0x70u))   /* SW128 for 128B rows */

#define CP_ASYNC16(dst, src) \
    asm volatile("cp.async.cg.shared.global [%0], [%1], 16;" \
                 :: "r"(dst), "l"(src) : "memory")
#define CP_COMMIT() asm volatile("cp.async.commit_group;" ::: "memory")
#define CP_WAIT(n)  asm volatile("cp.async.wait_group %0;" :: "n"(n) : "memory")

#define LDSM_X4(r0, r1, r2, r3, a) \
    asm volatile("ldmatrix.sync.aligned.m8n8.x4.shared.b16 {%0,%1,%2,%3}, [%4];" \
                 : "=r"(r0), "=r"(r1), "=r"(r2), "=r"(r3) : "r"(a))

#define MMA_BF16(c, a, b) \
    asm volatile("mma.sync.aligned.m16n8k16.row.col.f32.bf16.bf16.f32 " \
                 "{%0,%1,%2,%3},{%4,%5,%6,%7},{%8,%9},{%0,%1,%2,%3};" \
                 : "+f"((c)[0]), "+f"((c)[1]), "+f"((c)[2]), "+f"((c)[3]) \
                 : "r"((a)[0]), "r"((a)[1]), "r"((a)[2]), "r"((a)[3]), \
                   "r"((b)[0]), "r"((b)[1]))

__device__ __forceinline__ uint fkey(float f) {
    uint u = __float_as_uint(f);
    return (u & 0x80000000u) ? ~u : (u | 0x80000000u);
}
__device__ __forceinline__ float keyf(uint k) {
    uint u = (k & 0x80000000u) ? (k & 0x7fffffffu) : ~k;
    return __uint_as_float(u);
}

// ---------------------------------------------------------------------------
// K0: convert z and codebook to bf16.
// ---------------------------------------------------------------------------
__global__ void vq_convert_kernel(const float* __restrict__ z,
                                  const float* __restrict__ cb) {
    int i = blockIdx.x * blockDim.x + threadIdx.x;
    const int nz4 = ZQ_ELEMS / 4, nc4 = CB_ELEMS / 4;
    if (i < nz4) {
        float4 v = reinterpret_cast<const float4*>(z)[i];
        __nv_bfloat162 h0 = __floats2bfloat162_rn(v.x, v.y);
        __nv_bfloat162 h1 = __floats2bfloat162_rn(v.z, v.w);
        reinterpret_cast<uint2*>(g_zbf)[i] = make_uint2(*(uint*)&h0, *(uint*)&h1);
    } else if (i < nz4 + nc4) {
        int j = i - nz4;
        float4 v = reinterpret_cast<const float4*>(cb)[j];
        __nv_bfloat162 h0 = __floats2bfloat162_rn(v.x, v.y);
        __nv_bfloat162 h1 = __floats2bfloat162_rn(v.z, v.w);
        reinterpret_cast<uint2*>(g_cbbf)[j] = make_uint2(*(uint*)&h0, *(uint*)&h1);
    }
}

// ---------------------------------------------------------------------------
// K1: row norms + per-row state init + zero loss accumulator.
// ---------------------------------------------------------------------------
__global__ void vq_norms_kernel(const float* __restrict__ z,
                                const float* __restrict__ cb) {
    int gw   = (blockIdx.x * blockDim.x + threadIdx.x) >> 5;
    int lane = threadIdx.x & 31;
    if (gw == 0 && lane == 0) g_loss_acc = 0.0;
    if (gw >= M_ROWS + K_CODES) return;

    const float* src = (gw < M_ROWS) ? (z + (size_t)gw * D_DIM)
                                     : (cb + (size_t)(gw - M_ROWS) * D_DIM);
    float s = 0.f;
#pragma unroll
    for (int i = 0; i < D_DIM / 32; ++i) {
        float v = src[lane + i * 32];
        s = __fmaf_rn(v, v, s);
    }
#pragma unroll
    for (int off = 16; off > 0; off >>= 1)
        s = __fadd_rn(s, __shfl_xor_sync(0xffffffffu, s, off));
    if (lane == 0) {
        if (gw < M_ROWS) {
            g_znorm[gw]  = s;
            g_cnt[gw]    = 0;
            g_rowmin[gw] = 0xFFFFFFFFu;
        } else {
            g_enorm[gw - M_ROWS] = s;
        }
    }
}

// ---------------------------------------------------------------------------
// K2: A-resident screening GEMM.  CTA = 128 rows x 4096 codes.
// A: 4 sub-tiles of 128x64 (16KB each), loaded once.  B: 2-stage 16KB ring.
// 8 warps as 2(m) x 4(n), warp tile 64x32 (frag code identical to R5).
// Per-subtile epilogue, no barriers: s_rowmin via atomicMin (update -> read
// threshold -> collect; stale threshold is looser => superset => safe).
// ---------------------------------------------------------------------------
#define ACH_BYTES (GTM * KCH * 2)   /* 16384 per A sub-tile */
#define A_BYTES   (4 * ACH_BYTES)   /* 65536 */
#define B_BYTES   (GTN * KCH * 2)   /* 16384 per stage */
#define SMEM_DYN  (1024 + A_BYTES + 2 * B_BYTES)

__device__ __forceinline__ void load_b_chunk(uint bU, int kcBase, int cidx,
                                             int tid) {
    int sub = cidx >> 2, kc = cidx & 3;
#pragma unroll
    for (int i = 0; i < 4; ++i) {           // 128 codes x 8 16B-chunks
        int id = i * 256 + tid;
        int r = id >> 3, c = id & 7;
        const __nv_bfloat16* src =
            g_cbbf + (size_t)(kcBase + sub * GTN + r) * D_DIM + kc * KCH + c * 8;
        uint off = (uint)(r * 128 + c * 16);
        CP_ASYNC16(bU + SWZ(off), src);
    }
}

__global__ __launch_bounds__(256, 2) void vq_screen_kernel() {
    extern __shared__ __align__(16) char dynsmem[];
    __shared__ uint s_rowmin[GTM];

    const int tid  = threadIdx.x;
    const int wid  = tid >> 5, lane = tid & 31;
    const int rowBase = blockIdx.x * GTM;
    const int kcBase  = blockIdx.y * CPC;
    const int warp_m  = (wid >> 2) * 64;
    const int warp_n  = (wid & 3) * 32;

    uint base  = smem_u32(dynsmem);
    uint aBase = (base + 1023u) & ~1023u;
    uint bBase = aBase + A_BYTES;

    if (tid < GTM) s_rowmin[tid] = 0xFFFFFFFFu;

    // ---- load the full A tile (4 sub-tiles of 128x64) ----------------------
#pragma unroll
    for (int t = 0; t < 4; ++t) {
#pragma unroll
        for (int i = 0; i < 4; ++i) {
            int id = i * 256 + tid;
            int r = id >> 3, c = id & 7;
            const __nv_bfloat16* src =
                g_zbf + (size_t)(rowBase + r) * D_DIM + t * KCH + c * 8;
            uint off = (uint)(r * 128 + c * 16);
            CP_ASYNC16(aBase + t * ACH_BYTES + SWZ(off), src);
        }
    }
    load_b_chunk(bBase, kcBase, 0, tid);
    CP_COMMIT();

    float acc[4][4][4];
    float en_r[4][2];

    for (int cidx = 0; cidx < NCHUNK; ++cidx) {
        CP_WAIT(0);
        __syncthreads();          // chunk cidx visible; all warps done with
                                  // stage (cidx+1)&1 (read in iter cidx-1)
        if (cidx + 1 < NCHUNK) {
            load_b_chunk(bBase + ((cidx + 1) & 1) * B_BYTES, kcBase,
                         cidx + 1, tid);
            CP_COMMIT();
        }

        if ((cidx & 3) == 0) {    // subtile start: reset acc, prefetch enorm
            int sub = cidx >> 2;
#pragma unroll
            for (int mi = 0; mi < 4; ++mi)
#pragma unroll
                for (int ni = 0; ni < 4; ++ni)
#pragma unroll
                    for (int q = 0; q < 4; ++q) acc[mi][ni][q] = 0.f;
#pragma unroll
            for (int ni = 0; ni < 4; ++ni)
#pragma unroll
                for (int j = 0; j < 2; ++j)
                    en_r[ni][j] = g_enorm[kcBase + sub * GTN + warp_n + ni * 8
                                          + (lane & 3) * 2 + j];
        }

        uint aT = aBase + (cidx & 3) * ACH_BYTES;
        uint bT = bBase + (cidx & 1) * B_BYTES;
#pragma unroll
        for (int ks = 0; ks < KCH / 16; ++ks) {
            uint afr[4][4];
#pragma unroll
            for (int mi = 0; mi < 4; ++mi) {
                uint off = (uint)((warp_m + mi * 16 + (lane & 15)) * 128
                                  + ks * 32 + (lane >> 4) * 16);
                LDSM_X4(afr[mi][0], afr[mi][1], afr[mi][2], afr[mi][3],
                        aT + SWZ(off));
            }
            uint bfr[4][2];
#pragma unroll
            for (int np = 0; np < 2; ++np) {
                uint off = (uint)((warp_n + np * 16 + (lane & 7)
                                   + ((lane >> 4) & 1) * 8) * 128
                                  + ks * 32 + ((lane >> 3) & 1) * 16);
                LDSM_X4(bfr[np * 2][0], bfr[np * 2][1],
                        bfr[np * 2 + 1][0], bfr[np * 2 + 1][1],
                        bT + SWZ(off));
            }
#pragma unroll
            for (int mi = 0; mi < 4; ++mi)
#pragma unroll
                for (int ni = 0; ni < 4; ++ni)
                    MMA_BF16(acc[mi][ni], afr[mi], bfr[ni]);
        }

        if ((cidx & 3) == 3) {    // subtile end: epilogue (no barriers)
            int sub = cidx >> 2;
#pragma unroll
            for (int mi = 0; mi < 4; ++mi) {
#pragma unroll
                for (int h = 0; h < 2; ++h) {
                    int rl = warp_m + mi * 16 + h * 8 + (lane >> 2);
                    float m = 3.4028235e38f;
#pragma unroll
                    for (int ni = 0; ni < 4; ++ni)
#pragma unroll
                        for (int j = 0; j < 2; ++j) {
                            int q = h * 2 + j;
                            float d = __fmaf_rn(-2.f, acc[mi][ni][q],
                                                en_r[ni][j]);
                            acc[mi][ni][q] = d;
                            m = fminf(m, d);
                        }
                    atomicMin(&s_rowmin[rl], fkey(m));   // update FIRST
                    float thr = keyf(s_rowmin[rl]) + MARGIN;
                    int   row = rowBase + rl;
#pragma unroll
                    for (int ni = 0; ni < 4; ++ni)
#pragma unroll
                        for (int j = 0; j < 2; ++j) {
                            float d = acc[mi][ni][h * 2 + j];
                            if (d < thr) {
                                int code = kcBase + sub * GTN + warp_n + ni * 8
                                           + (lane & 3) * 2 + j;
                                int pos = atomicAdd(&g_cnt[row], 1);
                                if (pos < CAP)
                                    g_cand[(size_t)row * CAP + pos] =
                                        ((ull)__float_as_uint(d) << 32)
                                        | (uint)code;
                            }
                        }
                }
            }
        }
    }

    __syncthreads();
    if (tid < GTM)
        atomicMin(&g_rowmin[rowBase + tid], s_rowmin[tid]);
}

// ---------------------------------------------------------------------------
// K3: exact rescore.  One warp per row.
// ---------------------------------------------------------------------------
__global__ void vq_rescore_kernel(const float* __restrict__ z,
                                  const float* __restrict__ cb) {
    int gw   = (blockIdx.x * blockDim.x + threadIdx.x) >> 5;
    int lane = threadIdx.x & 31;
    if (gw >= M_ROWS) return;
    int row = gw;

    float zn     = g_znorm[row];
    float thresh = keyf(g_rowmin[row]) + MARGIN;
    int   cnt    = g_cnt[row];

    const float* zr = z + (size_t)row * D_DIM;
    float bestv = 3.4028235e38f;
    int   besti = K_CODES;

    if (cnt <= CAP) {
        for (int b = 0; b < cnt; b += 32) {
            int  i = b + lane;
            int  c = 0;
            bool q = false;
            if (i < cnt) {
                ull e = g_cand[(size_t)row * CAP + i];
                q = __uint_as_float((uint)(e >> 32)) < thresh;
                c = (int)(uint)(e & 0xffffffffull);
            }
            uint bal = __ballot_sync(0xffffffffu, q);
            while (bal) {
                int src = __ffs(bal) - 1; bal &= bal - 1;
                int cc  = __shfl_sync(0xffffffffu, c, src);
                const float* er = cb + (size_t)cc * D_DIM;
                float p = 0.f;
#pragma unroll
                for (int k = 0; k < 8; ++k)
                    p = __fmaf_rn(zr[lane + 32 * k], er[lane + 32 * k], p);
#pragma unroll
                for (int off = 16; off > 0; off >>= 1)
                    p = __fadd_rn(p, __shfl_xor_sync(0xffffffffu, p, off));
                float dv = __fmaf_rn(-2.f, p, __fadd_rn(zn, g_enorm[cc]));
                if (dv < bestv || (dv == bestv && cc < besti)) {
                    bestv = dv; besti = cc;
                }
            }
        }
    } else {
        for (int cc = 0; cc < K_CODES; ++cc) {   // overflow fallback
            const float* er = cb + (size_t)cc * D_DIM;
            float p = 0.f;
#pragma unroll
            for (int k = 0; k < 8; ++k)
                p = __fmaf_rn(zr[lane + 32 * k], er[lane + 32 * k], p);
#pragma unroll
            for (int off = 16; off > 0; off >>= 1)
                p = __fadd_rn(p, __shfl_xor_sync(0xffffffffu, p, off));
            float dv = __fmaf_rn(-2.f, p, __fadd_rn(zn, g_enorm[cc]));
            if (dv < bestv) { bestv = dv; besti = cc; }
        }
    }
    if (lane == 0) g_idx[row] = besti;
}

// ---------------------------------------------------------------------------
// K4: gather z_q, straight-through output, loss accumulation, index output.
// ---------------------------------------------------------------------------
__global__ void vq_gather_kernel(const float* __restrict__ z,
                                 const float* __restrict__ cb,
                                 float* __restrict__ out, int out_size) {
    int row = blockIdx.x;
    int t   = threadIdx.x;
    int idx = g_idx[row];

    float zq   = cb[(size_t)idx * D_DIM + t];
    float zv   = z [(size_t)row * D_DIM + t];
    float diff = __fadd_rn(zq, -zv);
    out[(size_t)row * D_DIM + t] = __fadd_rn(zv, diff);

    float sq = __fmul_rn(diff, diff);
#pragma unroll
    for (int off = 16; off > 0; off >>= 1)
        sq += __shfl_xor_sync(0xffffffffu, sq, off);

    __shared__ float warpS[8];
    if ((t & 31) == 0) warpS[t >> 5] = sq;
    __syncthreads();
    if (t == 0) {
        float s = 0.f;
#pragma unroll
        for (int w = 0; w < 8; ++w) s += warpS[w];
        atomicAdd(&g_loss_acc, (double)s);
        if (IDX_OFF + row < out_size) out[IDX_OFF + row] = (float)idx;
    }
}

__global__ void vq_finalize_kernel(float* __restrict__ out, int out_size) {
    if (LOSS_OFF < out_size)
        out[LOSS_OFF] = (float)(1.25 * g_loss_acc / (double)ZQ_ELEMS);
}

// ---------------------------------------------------------------------------
extern "C" void kernel_launch(void* const* d_in, const int* in_sizes, int n_in,
                              void* d_out, int out_size) {
    const float* z  = (const float*)d_in[0];
    const float* cb = (const float*)d_in[1];
    if (n_in >= 2 && in_sizes[0] == CB_ELEMS && in_sizes[1] == ZQ_ELEMS) {
        const float* tmp = z; z = cb; cb = tmp;
    }
    float* out = (float*)d_out;

    static bool attr_set = false;
    if (!attr_set) {
        cudaFuncSetAttribute(vq_screen_kernel,
                             cudaFuncAttributeMaxDynamicSharedMemorySize,
                             SMEM_DYN);
        attr_set = true;
    }

    int n4 = (ZQ_ELEMS + CB_ELEMS) / 4;
    vq_convert_kernel<<<(n4 + 255) / 256, 256>>>(z, cb);

    int nwarps = M_ROWS + K_CODES;
    vq_norms_kernel<<<(nwarps * 32 + 255) / 256, 256>>>(z, cb);

    dim3 sgrid(M_ROWS / GTM, NSPLIT);
    vq_screen_kernel<<<sgrid, 256, SMEM_DYN>>>();

    vq_rescore_kernel<<<(M_ROWS * 32 + 255) / 256, 256>>>(z, cb);

    vq_gather_kernel<<<M_ROWS, 256>>>(z, cb, out, out_size);
    vq_finalize_kernel<<<1, 1>>>(out, out_size);
}